// round 9
// baseline (speedup 1.0000x reference)
#include <cuda_runtime.h>

#define NN 100000
#define NE 1600000
#define SCAN_B 98           // ceil(100000 / 1024)

#define TILE_N 64
#define NTILES ((NN + TILE_N - 1) / TILE_N)   // 1563 (last tile partial)

// smem layout (floats) for fused GEMM kernel
#define W1T_SZ (8 * 1028)   // layer1 weights, 8 jt-regions, {wl,wr} interleaved, +4 pad
#define WPT_SZ (8 * 516)    // proj weights, 8 jtp-regions, {wl2,wr2} interleaved, +4 pad
#define AX_SZ  (64 * 130)   // 64 nodes x 64 k of {agg,x} float2, row 130 floats
#define SMEM_FLOATS (W1T_SZ + WPT_SZ + AX_SZ)
#define SMEM_BYTES  (SMEM_FLOATS * 4)         // 82688 B

// ---- scratch (static __device__ arrays; no allocation allowed) ----
__device__ int   g_is64;
__device__ int   g_cnt[NN];
__device__ int   g_scan[NN];
__device__ int   g_bsum[128];
__device__ int   g_rowstart[NN + 1];
__device__ int   g_cursor[NN];
__device__ int   g_csr[NE];
__device__ float g_p2[NN * 32];
__device__ float g_r2[NN * 32];

// ---- f32x2 packed helpers ----
__device__ __forceinline__ unsigned long long ffma2(
    unsigned long long a, unsigned long long b, unsigned long long c) {
    unsigned long long d;
    asm("fma.rn.f32x2 %0, %1, %2, %3;" : "=l"(d) : "l"(a), "l"(b), "l"(c));
    return d;
}
__device__ __forceinline__ unsigned long long pack2(float lo, float hi) {
    unsigned long long r;
    asm("mov.b64 %0, {%1, %2};" : "=l"(r) : "f"(lo), "f"(hi));
    return r;
}
__device__ __forceinline__ float2 unpack2(unsigned long long v) {
    float2 f;
    asm("mov.b64 {%0, %1}, %2;" : "=f"(f.x), "=f"(f.y) : "l"(v));
    return f;
}

// Detect int64 vs int32 edge_index.
__global__ void detect_kernel(const int* __restrict__ w) {
    int lane = threadIdx.x;
    int v = w[2 * lane + 1];
    unsigned m = __ballot_sync(0xffffffffu, v == 0);
    if (lane == 0) g_is64 = (m == 0xffffffffu) ? 1 : 0;
}

__global__ void zero_cnt_kernel() {
    int i = blockIdx.x * blockDim.x + threadIdx.x;
    if (i < NN / 4) ((int4*)g_cnt)[i] = make_int4(0, 0, 0, 0);
}

// Count in-degrees; reads only the dst half of edge_index.
__global__ void count_kernel(const void* __restrict__ e) {
    int i = blockIdx.x * blockDim.x + threadIdx.x;
    if (i >= NE) return;
    int d;
    if (g_is64) d = (int)((const long long*)e)[NE + i];
    else        d = ((const int*)e)[NE + i];
    atomicAdd(&g_cnt[d], 1);
}

__global__ void __launch_bounds__(1024) scanA_kernel() {
    __shared__ int s[1024];
    int t = threadIdx.x;
    int i = blockIdx.x * 1024 + t;
    int v = (i < NN) ? g_cnt[i] : 0;
    s[t] = v;
    __syncthreads();
#pragma unroll
    for (int off = 1; off < 1024; off <<= 1) {
        int tv = (t >= off) ? s[t - off] : 0;
        __syncthreads();
        s[t] += tv;
        __syncthreads();
    }
    if (i < NN) g_scan[i] = s[t];
    if (t == 1023) g_bsum[blockIdx.x] = s[t];
}

__global__ void __launch_bounds__(1024) scanB_kernel() {
    __shared__ int part[128];
    int t = threadIdx.x;
    if (t < 128) part[t] = (t < blockIdx.x && t < SCAN_B) ? g_bsum[t] : 0;
    __syncthreads();
#pragma unroll
    for (int off = 64; off > 0; off >>= 1) {
        if (t < off) part[t] += part[t + off];
        __syncthreads();
    }
    int offset = part[0];
    int i = blockIdx.x * 1024 + t;
    if (i < NN) {
        int rs = offset + g_scan[i] - g_cnt[i];
        g_rowstart[i] = rs;
        g_cursor[i] = rs;
    }
    if (i == 0) g_rowstart[NN] = NE;
}

// Fill CSR: read edge_index directly, convert inline.
__global__ void __launch_bounds__(256) fill_kernel(const void* __restrict__ e) {
    int i = blockIdx.x * 256 + threadIdx.x;
    if (i >= NE) return;
    int s, d;
    if (g_is64) {
        const long long* p = (const long long*)e;
        s = (int)p[i];
        d = (int)p[NE + i];
    } else {
        const int* p = (const int*)e;
        s = p[i];
        d = p[NE + i];
    }
    int pos = atomicAdd(&g_cursor[d], 1);
    g_csr[pos] = s;
}

// Fused gather1 + layer1 + proj (packed f32x2):
//   gather: per-tile mean of neighbor x rows -> sAX {agg,x} pairs (smem)
//   main:   acc_j{aggpart,xpart} += {A,X} * {wl,wr}  -> h = relu(lo+hi+b1)
//   proj:   acc_j{p2,r2} += {h,h} * {wl2,wr2}        -> g_p2, g_r2
__global__ void __launch_bounds__(256) gemm_fused_kernel(
    const float* __restrict__ x,
    const float* __restrict__ Wl1, const float* __restrict__ Wr1,
    const float* __restrict__ b1,
    const float* __restrict__ Wl2, const float* __restrict__ Wr2) {
    extern __shared__ float smem[];
    float* sW1T = smem;                 // [8][1028]
    float* sWPT = smem + W1T_SZ;        // [8][516]
    float* sAX  = smem + W1T_SZ + WPT_SZ;   // [64][130] float2-interleaved
    float* sH   = sAX;                  // overlay: [64][68] after main loop

    int tid = threadIdx.x;
    // stage layer1 weights interleaved {wl, wr}, per-jt region (pad 4 -> bank shift)
    for (int i = tid; i < 64 * 64; i += 256) {
        int k = i >> 6, j = i & 63;
        int jt = j >> 3, jj = j & 7;
        sW1T[jt * 1028 + k * 16 + jj * 2 + 0] = Wl1[k * 64 + j];
        sW1T[jt * 1028 + k * 16 + jj * 2 + 1] = Wr1[k * 64 + j];
    }
    // stage proj weights interleaved {wl2, wr2}, per-jtp region
    for (int i = tid; i < 64 * 32; i += 256) {
        int k = i >> 5, j = i & 31;
        int jtp = j >> 2, jj = j & 3;
        sWPT[jtp * 516 + k * 8 + jj * 2 + 0] = Wl2[k * 32 + j];
        sWPT[jtp * 516 + k * 8 + jj * 2 + 1] = Wr2[k * 32 + j];
    }
    int ln = tid >> 3, jt = tid & 7;    // main: 32 node-pairs x 8 j-groups(8 j each)
    int gc = tid & 15, gg = tid >> 4;   // gather: chunk 0..15, node-group 0..15
    float bb[8];
    {
        float4 ba = __ldg(&((const float4*)b1)[jt * 2]);
        float4 bc = __ldg(&((const float4*)b1)[jt * 2 + 1]);
        bb[0] = ba.x; bb[1] = ba.y; bb[2] = ba.z; bb[3] = ba.w;
        bb[4] = bc.x; bb[5] = bc.y; bb[6] = bc.z; bb[7] = bc.w;
    }
    const float4* x4 = (const float4*)x;

    for (int tile = blockIdx.x; tile < NTILES; tile += gridDim.x) {
        int base = tile * TILE_N;
        __syncthreads();   // previous iteration's proj reads of sH done
        // gather: 4 nodes per thread (gg, gg+16, gg+32, gg+48), chunk gc
#pragma unroll
        for (int q = 0; q < 4; q++) {
            int node = gg + q * 16;
            int n = base + node;
            float4 a = make_float4(0.f, 0.f, 0.f, 0.f);
            float4 xv = make_float4(0.f, 0.f, 0.f, 0.f);
            if (n < NN) {
                xv = __ldg(&x4[n * 16 + gc]);
                int beg = __ldg(&g_rowstart[n]), end = __ldg(&g_rowstart[n + 1]);
                int e = beg;
                for (; e + 3 < end; e += 4) {
                    int s0 = __ldg(&g_csr[e]);
                    int s1 = __ldg(&g_csr[e + 1]);
                    int s2 = __ldg(&g_csr[e + 2]);
                    int s3 = __ldg(&g_csr[e + 3]);
                    float4 v0 = __ldg(&x4[s0 * 16 + gc]);
                    float4 v1 = __ldg(&x4[s1 * 16 + gc]);
                    float4 v2 = __ldg(&x4[s2 * 16 + gc]);
                    float4 v3 = __ldg(&x4[s3 * 16 + gc]);
                    a.x += (v0.x + v1.x) + (v2.x + v3.x);
                    a.y += (v0.y + v1.y) + (v2.y + v3.y);
                    a.z += (v0.z + v1.z) + (v2.z + v3.z);
                    a.w += (v0.w + v1.w) + (v2.w + v3.w);
                }
                for (; e < end; e++) {
                    int s = __ldg(&g_csr[e]);
                    float4 v = __ldg(&x4[s * 16 + gc]);
                    a.x += v.x; a.y += v.y; a.z += v.z; a.w += v.w;
                }
                float inv = 1.f / fmaxf((float)(end - beg), 1.f);
                a.x *= inv; a.y *= inv; a.z *= inv; a.w *= inv;
            }
            float2* dst = (float2*)(sAX + node * 130 + gc * 8);
            dst[0] = make_float2(a.x, xv.x);
            dst[1] = make_float2(a.y, xv.y);
            dst[2] = make_float2(a.z, xv.z);
            dst[3] = make_float2(a.w, xv.w);
        }
        __syncthreads();
        // main GEMM: 2 nodes x 8 outputs per thread
        {
            const unsigned long long* ax0p = (const unsigned long long*)(sAX + (2 * ln) * 130);
            const unsigned long long* ax1p = (const unsigned long long*)(sAX + (2 * ln + 1) * 130);
            const unsigned long long* wp = (const unsigned long long*)(sW1T + jt * 1028);
            unsigned long long acc0[8], acc1[8];
#pragma unroll
            for (int j = 0; j < 8; j++) { acc0[j] = 0ull; acc1[j] = 0ull; }
#pragma unroll 8
            for (int k = 0; k < 64; k++) {
                unsigned long long ax0 = ax0p[k];
                unsigned long long ax1 = ax1p[k];
                ulonglong2 wA = ((const ulonglong2*)(wp + k * 8))[0];
                ulonglong2 wB = ((const ulonglong2*)(wp + k * 8))[1];
                ulonglong2 wC = ((const ulonglong2*)(wp + k * 8))[2];
                ulonglong2 wD = ((const ulonglong2*)(wp + k * 8))[3];
                acc0[0] = ffma2(ax0, wA.x, acc0[0]); acc1[0] = ffma2(ax1, wA.x, acc1[0]);
                acc0[1] = ffma2(ax0, wA.y, acc0[1]); acc1[1] = ffma2(ax1, wA.y, acc1[1]);
                acc0[2] = ffma2(ax0, wB.x, acc0[2]); acc1[2] = ffma2(ax1, wB.x, acc1[2]);
                acc0[3] = ffma2(ax0, wB.y, acc0[3]); acc1[3] = ffma2(ax1, wB.y, acc1[3]);
                acc0[4] = ffma2(ax0, wC.x, acc0[4]); acc1[4] = ffma2(ax1, wC.x, acc1[4]);
                acc0[5] = ffma2(ax0, wC.y, acc0[5]); acc1[5] = ffma2(ax1, wC.y, acc1[5]);
                acc0[6] = ffma2(ax0, wD.x, acc0[6]); acc1[6] = ffma2(ax1, wD.x, acc1[6]);
                acc0[7] = ffma2(ax0, wD.y, acc0[7]); acc1[7] = ffma2(ax1, wD.y, acc1[7]);
            }
            __syncthreads();   // all reads of sAX done before sH overlay
            float h0[8], h1[8];
#pragma unroll
            for (int j = 0; j < 8; j++) {
                float2 f0 = unpack2(acc0[j]);
                float2 f1 = unpack2(acc1[j]);
                h0[j] = fmaxf(f0.x + f0.y + bb[j], 0.f);
                h1[j] = fmaxf(f1.x + f1.y + bb[j], 0.f);
            }
            float4* d0 = (float4*)(sH + (2 * ln) * 68 + jt * 8);
            float4* d1 = (float4*)(sH + (2 * ln + 1) * 68 + jt * 8);
            d0[0] = make_float4(h0[0], h0[1], h0[2], h0[3]);
            d0[1] = make_float4(h0[4], h0[5], h0[6], h0[7]);
            d1[0] = make_float4(h1[0], h1[1], h1[2], h1[3]);
            d1[1] = make_float4(h1[4], h1[5], h1[6], h1[7]);
        }
        __syncthreads();
        // proj: 2 nodes x 4 {p2,r2}-pairs per thread
        {
            const float* h0p = sH + (2 * ln) * 68;
            const float* h1p = sH + (2 * ln + 1) * 68;
            const unsigned long long* wpp = (const unsigned long long*)(sWPT + jt * 516);
            unsigned long long pa0[4], pa1[4];
#pragma unroll
            for (int j = 0; j < 4; j++) { pa0[j] = 0ull; pa1[j] = 0ull; }
#pragma unroll 8
            for (int k = 0; k < 64; k++) {
                float hv0 = h0p[k], hv1 = h1p[k];
                unsigned long long hh0 = pack2(hv0, hv0);
                unsigned long long hh1 = pack2(hv1, hv1);
                ulonglong2 w01 = ((const ulonglong2*)(wpp + k * 4))[0];
                ulonglong2 w23 = ((const ulonglong2*)(wpp + k * 4))[1];
                pa0[0] = ffma2(hh0, w01.x, pa0[0]); pa1[0] = ffma2(hh1, w01.x, pa1[0]);
                pa0[1] = ffma2(hh0, w01.y, pa0[1]); pa1[1] = ffma2(hh1, w01.y, pa1[1]);
                pa0[2] = ffma2(hh0, w23.x, pa0[2]); pa1[2] = ffma2(hh1, w23.x, pa1[2]);
                pa0[3] = ffma2(hh0, w23.y, pa0[3]); pa1[3] = ffma2(hh1, w23.y, pa1[3]);
            }
            int n0 = base + 2 * ln, n1 = n0 + 1;
            float p0[4], r0[4], p1[4], r1[4];
#pragma unroll
            for (int j = 0; j < 4; j++) {
                float2 f0 = unpack2(pa0[j]);
                float2 f1 = unpack2(pa1[j]);
                p0[j] = f0.x; r0[j] = f0.y;
                p1[j] = f1.x; r1[j] = f1.y;
            }
            if (n0 < NN) {
                ((float4*)g_p2)[n0 * 8 + jt] = make_float4(p0[0], p0[1], p0[2], p0[3]);
                ((float4*)g_r2)[n0 * 8 + jt] = make_float4(r0[0], r0[1], r0[2], r0[3]);
            }
            if (n1 < NN) {
                ((float4*)g_p2)[n1 * 8 + jt] = make_float4(p1[0], p1[1], p1[2], p1[3]);
                ((float4*)g_r2)[n1 * 8 + jt] = make_float4(r1[0], r1[1], r1[2], r1[3]);
            }
        }
    }
}

// Final fused: gather2 (mean of p2 over neighbors) + root + bias -> out,
// then trust head (32->16 relu -> 16->1 sigmoid) via warp shuffles.
__global__ void __launch_bounds__(256) final_kernel(
    const float* __restrict__ b2, const float* __restrict__ Wt1,
    const float* __restrict__ bt1, const float* __restrict__ Wt2,
    const float* __restrict__ bt2, float* __restrict__ out) {
    __shared__ float sW1[32 * 16], sB2[32], sBt1[16], sW2[16];
    __shared__ float sBt2;
    int tid = threadIdx.x;
    sW1[tid] = Wt1[tid];
    sW1[tid + 256] = Wt1[tid + 256];
    if (tid < 32) sB2[tid] = b2[tid];
    if (tid < 16) { sBt1[tid] = bt1[tid]; sW2[tid] = Wt2[tid]; }
    if (tid == 0) sBt2 = bt2[0];
    __syncthreads();
    int warp = tid >> 5, lane = tid & 31;
    int n = blockIdx.x * 8 + warp;   // 12500 * 8 == 100000 exactly
    int beg = g_rowstart[n], end = g_rowstart[n + 1];
    float acc = 0.f;
#pragma unroll 4
    for (int e = beg; e < end; e++) {
        int s = __ldg(&g_csr[e]);
        acc += __ldg(&g_p2[s * 32 + lane]);
    }
    float inv = 1.f / fmaxf((float)(end - beg), 1.f);
    float v = acc * inv + g_r2[n * 32 + lane] + sB2[lane];
    out[n * 32 + lane] = v;
    float a2 = (lane < 16) ? sBt1[lane] : 0.f;
    int o = lane & 15;
#pragma unroll
    for (int j = 0; j < 32; j++) {
        float hv = __shfl_sync(0xffffffffu, v, j);
        a2 += hv * sW1[j * 16 + o];
    }
    float t = fmaxf(a2, 0.f) * sW2[o];
    t += __shfl_down_sync(0xffffffffu, t, 8);
    t += __shfl_down_sync(0xffffffffu, t, 4);
    t += __shfl_down_sync(0xffffffffu, t, 2);
    t += __shfl_down_sync(0xffffffffu, t, 1);
    if (lane == 0)
        out[NN * 32 + n] = 1.f / (1.f + __expf(-(t + sBt2)));
}

extern "C" void kernel_launch(void* const* d_in, const int* in_sizes, int n_in,
                              void* d_out, int out_size) {
    const float* x   = (const float*)d_in[0];
    const void*  ei  = d_in[1];
    const float* Wl1 = (const float*)d_in[2];
    const float* Wr1 = (const float*)d_in[3];
    const float* b1  = (const float*)d_in[4];
    const float* Wl2 = (const float*)d_in[5];
    const float* Wr2 = (const float*)d_in[6];
    const float* b2  = (const float*)d_in[7];
    const float* Wt1 = (const float*)d_in[8];
    const float* bt1 = (const float*)d_in[9];
    const float* Wt2 = (const float*)d_in[10];
    const float* bt2 = (const float*)d_in[11];
    float* out = (float*)d_out;

    cudaFuncSetAttribute(gemm_fused_kernel,
                         cudaFuncAttributeMaxDynamicSharedMemorySize, SMEM_BYTES);

    detect_kernel<<<1, 32>>>((const int*)ei);
    zero_cnt_kernel<<<(NN / 4 + 255) / 256, 256>>>();
    count_kernel<<<(NE + 255) / 256, 256>>>(ei);
    scanA_kernel<<<SCAN_B, 1024>>>();
    scanB_kernel<<<SCAN_B, 1024>>>();
    fill_kernel<<<(NE + 255) / 256, 256>>>(ei);
    gemm_fused_kernel<<<296, 256, SMEM_BYTES>>>(x, Wl1, Wr1, b1, Wl2, Wr2);
    final_kernel<<<NN / 8, 256>>>(b2, Wt1, bt1, Wt2, bt2, out);
}

// round 10
// speedup vs baseline: 1.0992x; 1.0992x over previous
#include <cuda_runtime.h>

#define NN 100000
#define NE 1600000
#define SCAN_B 98           // ceil(100000 / 1024)

#define TILE_N 64
#define NTILES ((NN + TILE_N - 1) / TILE_N)   // 1563 (last tile partial)

// smem layout (floats) for fused GEMM kernel
#define W1T_SZ (8 * 1028)   // layer1 weights, 8 jt-regions, {wl,wr} interleaved, +4 pad
#define WPT_SZ (8 * 516)    // proj weights, 8 jtp-regions, {wl2,wr2} interleaved, +4 pad
#define AX_SZ  (64 * 130)   // 64 nodes x 64 k of {agg,x} float2, row 130 floats
#define SMEM_FLOATS (W1T_SZ + WPT_SZ + AX_SZ)
#define SMEM_BYTES  (SMEM_FLOATS * 4)         // 82688 B

// ---- scratch (static __device__ arrays; no allocation allowed) ----
__device__ int   g_is64;
__device__ int   g_cnt[NN];
__device__ int   g_scan[NN];
__device__ int   g_bsum[128];
__device__ int   g_rowstart[NN + 1];
__device__ int   g_cursor[NN];
__device__ int   g_csr[NE];
__device__ float g_agg1[NN * 64];
__device__ float g_p2[NN * 32];
__device__ float g_r2[NN * 32];

// ---- f32x2 packed helpers ----
__device__ __forceinline__ unsigned long long ffma2(
    unsigned long long a, unsigned long long b, unsigned long long c) {
    unsigned long long d;
    asm("fma.rn.f32x2 %0, %1, %2, %3;" : "=l"(d) : "l"(a), "l"(b), "l"(c));
    return d;
}
__device__ __forceinline__ unsigned long long pack2(float lo, float hi) {
    unsigned long long r;
    asm("mov.b64 %0, {%1, %2};" : "=l"(r) : "f"(lo), "f"(hi));
    return r;
}
__device__ __forceinline__ float2 unpack2(unsigned long long v) {
    float2 f;
    asm("mov.b64 {%0, %1}, %2;" : "=f"(f.x), "=f"(f.y) : "l"(v));
    return f;
}

// Detect int64 vs int32 edge_index.
__global__ void detect_kernel(const int* __restrict__ w) {
    int lane = threadIdx.x;
    int v = w[2 * lane + 1];
    unsigned m = __ballot_sync(0xffffffffu, v == 0);
    if (lane == 0) g_is64 = (m == 0xffffffffu) ? 1 : 0;
}

__global__ void zero_cnt_kernel() {
    int i = blockIdx.x * blockDim.x + threadIdx.x;
    if (i < NN / 4) ((int4*)g_cnt)[i] = make_int4(0, 0, 0, 0);
}

// Count in-degrees; reads only the dst half of edge_index.
__global__ void count_kernel(const void* __restrict__ e) {
    int i = blockIdx.x * blockDim.x + threadIdx.x;
    if (i >= NE) return;
    int d;
    if (g_is64) d = (int)((const long long*)e)[NE + i];
    else        d = ((const int*)e)[NE + i];
    atomicAdd(&g_cnt[d], 1);
}

__global__ void __launch_bounds__(1024) scanA_kernel() {
    __shared__ int s[1024];
    int t = threadIdx.x;
    int i = blockIdx.x * 1024 + t;
    int v = (i < NN) ? g_cnt[i] : 0;
    s[t] = v;
    __syncthreads();
#pragma unroll
    for (int off = 1; off < 1024; off <<= 1) {
        int tv = (t >= off) ? s[t - off] : 0;
        __syncthreads();
        s[t] += tv;
        __syncthreads();
    }
    if (i < NN) g_scan[i] = s[t];
    if (t == 1023) g_bsum[blockIdx.x] = s[t];
}

__global__ void __launch_bounds__(1024) scanB_kernel() {
    __shared__ int part[128];
    int t = threadIdx.x;
    if (t < 128) part[t] = (t < blockIdx.x && t < SCAN_B) ? g_bsum[t] : 0;
    __syncthreads();
#pragma unroll
    for (int off = 64; off > 0; off >>= 1) {
        if (t < off) part[t] += part[t + off];
        __syncthreads();
    }
    int offset = part[0];
    int i = blockIdx.x * 1024 + t;
    if (i < NN) {
        int rs = offset + g_scan[i] - g_cnt[i];
        g_rowstart[i] = rs;
        g_cursor[i] = rs;
    }
    if (i == 0) g_rowstart[NN] = NE;
}

// Fill CSR: read edge_index directly, convert inline.
__global__ void __launch_bounds__(256) fill_kernel(const void* __restrict__ e) {
    int i = blockIdx.x * 256 + threadIdx.x;
    if (i >= NE) return;
    int s, d;
    if (g_is64) {
        const long long* p = (const long long*)e;
        s = (int)p[i];
        d = (int)p[NE + i];
    } else {
        const int* p = (const int*)e;
        s = p[i];
        d = p[NE + i];
    }
    int pos = atomicAdd(&g_cursor[d], 1);
    g_csr[pos] = s;
}

// Gather layer 1: agg1[n] = mean over neighbors of x[src]. Thread=(node,chunk).
// Massively parallel (1.6M threads) so variable-degree latency is hidden.
__global__ void __launch_bounds__(256) gather1_kernel(const float* __restrict__ x) {
    int idx = blockIdx.x * 256 + threadIdx.x;
    int n = idx >> 4, c = idx & 15;
    if (n >= NN) return;
    int beg = __ldg(&g_rowstart[n]), end = __ldg(&g_rowstart[n + 1]);
    float4 acc = make_float4(0.f, 0.f, 0.f, 0.f);
#pragma unroll 4
    for (int e = beg; e < end; e++) {
        int s = __ldg(&g_csr[e]);                 // broadcast across 16 lanes
        float4 v = __ldg(&((const float4*)x)[s * 16 + c]);
        acc.x += v.x; acc.y += v.y; acc.z += v.z; acc.w += v.w;
    }
    float inv = 1.f / fmaxf((float)(end - beg), 1.f);
    acc.x *= inv; acc.y *= inv; acc.z *= inv; acc.w *= inv;
    ((float4*)g_agg1)[n * 16 + c] = acc;
}

// Fused layer1 + proj, packed f32x2:
//   main: acc_j{aggpart,xpart} += {A,X} * {wl,wr}  -> h = relu(lo+hi+b1)
//   proj: acc_j{p2,r2} += {h,h} * {wl2,wr2}        -> g_p2, g_r2
__global__ void __launch_bounds__(256) gemm_fused_kernel(
    const float* __restrict__ x,
    const float* __restrict__ Wl1, const float* __restrict__ Wr1,
    const float* __restrict__ b1,
    const float* __restrict__ Wl2, const float* __restrict__ Wr2) {
    extern __shared__ float smem[];
    float* sW1T = smem;                 // [8][1028]
    float* sWPT = smem + W1T_SZ;        // [8][516]
    float* sAX  = smem + W1T_SZ + WPT_SZ;   // [64][130] float2-interleaved
    float* sH   = sAX;                  // overlay: [64][68] after main loop

    int tid = threadIdx.x;
    // stage layer1 weights interleaved {wl, wr}, per-jt region (pad 4 -> bank shift)
    for (int i = tid; i < 64 * 64; i += 256) {
        int k = i >> 6, j = i & 63;
        int jt = j >> 3, jj = j & 7;
        sW1T[jt * 1028 + k * 16 + jj * 2 + 0] = Wl1[k * 64 + j];
        sW1T[jt * 1028 + k * 16 + jj * 2 + 1] = Wr1[k * 64 + j];
    }
    // stage proj weights interleaved {wl2, wr2}, per-jtp region
    for (int i = tid; i < 64 * 32; i += 256) {
        int k = i >> 5, j = i & 31;
        int jtp = j >> 2, jj = j & 3;
        sWPT[jtp * 516 + k * 8 + jj * 2 + 0] = Wl2[k * 32 + j];
        sWPT[jtp * 516 + k * 8 + jj * 2 + 1] = Wr2[k * 32 + j];
    }
    int ln = tid >> 3, jt = tid & 7;    // main: 32 node-pairs x 8 j-groups(8 j each)
    float bb[8];
    {
        float4 ba = __ldg(&((const float4*)b1)[jt * 2]);
        float4 bc = __ldg(&((const float4*)b1)[jt * 2 + 1]);
        bb[0] = ba.x; bb[1] = ba.y; bb[2] = ba.z; bb[3] = ba.w;
        bb[4] = bc.x; bb[5] = bc.y; bb[6] = bc.z; bb[7] = bc.w;
    }
    const float4* agg4 = (const float4*)g_agg1;
    const float4* x4 = (const float4*)x;

    for (int tile = blockIdx.x; tile < NTILES; tile += gridDim.x) {
        int base = tile * TILE_N;
        __syncthreads();   // previous iteration's proj reads of sH done
        // stage sAX: node-local rows of {agg, x} pairs
        for (int u = tid; u < 64 * 16; u += 256) {
            int node = u >> 4, c = u & 15;     // c = float4 chunk (k = 4c..4c+3)
            int n = base + node;
            float4 a, xv;
            if (n < NN) { a = agg4[n * 16 + c]; xv = x4[n * 16 + c]; }
            else { a = make_float4(0.f,0.f,0.f,0.f); xv = a; }
            float2* dst = (float2*)(sAX + node * 130 + c * 8);
            dst[0] = make_float2(a.x, xv.x);
            dst[1] = make_float2(a.y, xv.y);
            dst[2] = make_float2(a.z, xv.z);
            dst[3] = make_float2(a.w, xv.w);
        }
        __syncthreads();
        // main GEMM: 2 nodes x 8 outputs per thread
        {
            const unsigned long long* ax0p = (const unsigned long long*)(sAX + (2 * ln) * 130);
            const unsigned long long* ax1p = (const unsigned long long*)(sAX + (2 * ln + 1) * 130);
            const unsigned long long* wp = (const unsigned long long*)(sW1T + jt * 1028);
            unsigned long long acc0[8], acc1[8];
#pragma unroll
            for (int j = 0; j < 8; j++) { acc0[j] = 0ull; acc1[j] = 0ull; }
#pragma unroll 8
            for (int k = 0; k < 64; k++) {
                unsigned long long ax0 = ax0p[k];
                unsigned long long ax1 = ax1p[k];
                ulonglong2 wA = ((const ulonglong2*)(wp + k * 8))[0];
                ulonglong2 wB = ((const ulonglong2*)(wp + k * 8))[1];
                ulonglong2 wC = ((const ulonglong2*)(wp + k * 8))[2];
                ulonglong2 wD = ((const ulonglong2*)(wp + k * 8))[3];
                acc0[0] = ffma2(ax0, wA.x, acc0[0]); acc1[0] = ffma2(ax1, wA.x, acc1[0]);
                acc0[1] = ffma2(ax0, wA.y, acc0[1]); acc1[1] = ffma2(ax1, wA.y, acc1[1]);
                acc0[2] = ffma2(ax0, wB.x, acc0[2]); acc1[2] = ffma2(ax1, wB.x, acc1[2]);
                acc0[3] = ffma2(ax0, wB.y, acc0[3]); acc1[3] = ffma2(ax1, wB.y, acc1[3]);
                acc0[4] = ffma2(ax0, wC.x, acc0[4]); acc1[4] = ffma2(ax1, wC.x, acc1[4]);
                acc0[5] = ffma2(ax0, wC.y, acc0[5]); acc1[5] = ffma2(ax1, wC.y, acc1[5]);
                acc0[6] = ffma2(ax0, wD.x, acc0[6]); acc1[6] = ffma2(ax1, wD.x, acc1[6]);
                acc0[7] = ffma2(ax0, wD.y, acc0[7]); acc1[7] = ffma2(ax1, wD.y, acc1[7]);
            }
            __syncthreads();   // all reads of sAX done before sH overlay
            float h0[8], h1[8];
#pragma unroll
            for (int j = 0; j < 8; j++) {
                float2 f0 = unpack2(acc0[j]);
                float2 f1 = unpack2(acc1[j]);
                h0[j] = fmaxf(f0.x + f0.y + bb[j], 0.f);
                h1[j] = fmaxf(f1.x + f1.y + bb[j], 0.f);
            }
            float4* d0 = (float4*)(sH + (2 * ln) * 68 + jt * 8);
            float4* d1 = (float4*)(sH + (2 * ln + 1) * 68 + jt * 8);
            d0[0] = make_float4(h0[0], h0[1], h0[2], h0[3]);
            d0[1] = make_float4(h0[4], h0[5], h0[6], h0[7]);
            d1[0] = make_float4(h1[0], h1[1], h1[2], h1[3]);
            d1[1] = make_float4(h1[4], h1[5], h1[6], h1[7]);
        }
        __syncthreads();
        // proj: 2 nodes x 4 {p2,r2}-pairs per thread
        {
            const float* h0p = sH + (2 * ln) * 68;
            const float* h1p = sH + (2 * ln + 1) * 68;
            const unsigned long long* wpp = (const unsigned long long*)(sWPT + jt * 516);
            unsigned long long pa0[4], pa1[4];
#pragma unroll
            for (int j = 0; j < 4; j++) { pa0[j] = 0ull; pa1[j] = 0ull; }
#pragma unroll 8
            for (int k = 0; k < 64; k++) {
                float hv0 = h0p[k], hv1 = h1p[k];
                unsigned long long hh0 = pack2(hv0, hv0);
                unsigned long long hh1 = pack2(hv1, hv1);
                ulonglong2 w01 = ((const ulonglong2*)(wpp + k * 4))[0];
                ulonglong2 w23 = ((const ulonglong2*)(wpp + k * 4))[1];
                pa0[0] = ffma2(hh0, w01.x, pa0[0]); pa1[0] = ffma2(hh1, w01.x, pa1[0]);
                pa0[1] = ffma2(hh0, w01.y, pa0[1]); pa1[1] = ffma2(hh1, w01.y, pa1[1]);
                pa0[2] = ffma2(hh0, w23.x, pa0[2]); pa1[2] = ffma2(hh1, w23.x, pa1[2]);
                pa0[3] = ffma2(hh0, w23.y, pa0[3]); pa1[3] = ffma2(hh1, w23.y, pa1[3]);
            }
            int n0 = base + 2 * ln, n1 = n0 + 1;
            float p0[4], r0[4], p1[4], r1[4];
#pragma unroll
            for (int j = 0; j < 4; j++) {
                float2 f0 = unpack2(pa0[j]);
                float2 f1 = unpack2(pa1[j]);
                p0[j] = f0.x; r0[j] = f0.y;
                p1[j] = f1.x; r1[j] = f1.y;
            }
            if (n0 < NN) {
                ((float4*)g_p2)[n0 * 8 + jt] = make_float4(p0[0], p0[1], p0[2], p0[3]);
                ((float4*)g_r2)[n0 * 8 + jt] = make_float4(r0[0], r0[1], r0[2], r0[3]);
            }
            if (n1 < NN) {
                ((float4*)g_p2)[n1 * 8 + jt] = make_float4(p1[0], p1[1], p1[2], p1[3]);
                ((float4*)g_r2)[n1 * 8 + jt] = make_float4(r1[0], r1[1], r1[2], r1[3]);
            }
        }
    }
}

// Final fused: gather2 (mean of p2 over neighbors) + root + bias -> out,
// then trust head (32->16 relu -> 16->1 sigmoid) via warp shuffles.
__global__ void __launch_bounds__(256) final_kernel(
    const float* __restrict__ b2, const float* __restrict__ Wt1,
    const float* __restrict__ bt1, const float* __restrict__ Wt2,
    const float* __restrict__ bt2, float* __restrict__ out) {
    __shared__ float sW1[32 * 16], sB2[32], sBt1[16], sW2[16];
    __shared__ float sBt2;
    int tid = threadIdx.x;
    sW1[tid] = Wt1[tid];
    sW1[tid + 256] = Wt1[tid + 256];
    if (tid < 32) sB2[tid] = b2[tid];
    if (tid < 16) { sBt1[tid] = bt1[tid]; sW2[tid] = Wt2[tid]; }
    if (tid == 0) sBt2 = bt2[0];
    __syncthreads();
    int warp = tid >> 5, lane = tid & 31;
    int n = blockIdx.x * 8 + warp;   // 12500 * 8 == 100000 exactly
    int beg = __ldg(&g_rowstart[n]), end = __ldg(&g_rowstart[n + 1]);
    float acc = 0.f;
#pragma unroll 4
    for (int e = beg; e < end; e++) {
        int s = __ldg(&g_csr[e]);
        acc += __ldg(&g_p2[s * 32 + lane]);
    }
    float inv = 1.f / fmaxf((float)(end - beg), 1.f);
    float v = acc * inv + g_r2[n * 32 + lane] + sB2[lane];
    out[n * 32 + lane] = v;
    float a2 = (lane < 16) ? sBt1[lane] : 0.f;
    int o = lane & 15;
#pragma unroll
    for (int j = 0; j < 32; j++) {
        float hv = __shfl_sync(0xffffffffu, v, j);
        a2 += hv * sW1[j * 16 + o];
    }
    float t = fmaxf(a2, 0.f) * sW2[o];
    t += __shfl_down_sync(0xffffffffu, t, 8);
    t += __shfl_down_sync(0xffffffffu, t, 4);
    t += __shfl_down_sync(0xffffffffu, t, 2);
    t += __shfl_down_sync(0xffffffffu, t, 1);
    if (lane == 0)
        out[NN * 32 + n] = 1.f / (1.f + __expf(-(t + sBt2)));
}

extern "C" void kernel_launch(void* const* d_in, const int* in_sizes, int n_in,
                              void* d_out, int out_size) {
    const float* x   = (const float*)d_in[0];
    const void*  ei  = d_in[1];
    const float* Wl1 = (const float*)d_in[2];
    const float* Wr1 = (const float*)d_in[3];
    const float* b1  = (const float*)d_in[4];
    const float* Wl2 = (const float*)d_in[5];
    const float* Wr2 = (const float*)d_in[6];
    const float* b2  = (const float*)d_in[7];
    const float* Wt1 = (const float*)d_in[8];
    const float* bt1 = (const float*)d_in[9];
    const float* Wt2 = (const float*)d_in[10];
    const float* bt2 = (const float*)d_in[11];
    float* out = (float*)d_out;

    cudaFuncSetAttribute(gemm_fused_kernel,
                         cudaFuncAttributeMaxDynamicSharedMemorySize, SMEM_BYTES);

    detect_kernel<<<1, 32>>>((const int*)ei);
    zero_cnt_kernel<<<(NN / 4 + 255) / 256, 256>>>();
    count_kernel<<<(NE + 255) / 256, 256>>>(ei);
    scanA_kernel<<<SCAN_B, 1024>>>();
    scanB_kernel<<<SCAN_B, 1024>>>();
    fill_kernel<<<(NE + 255) / 256, 256>>>(ei);
    gather1_kernel<<<(NN * 16 + 255) / 256, 256>>>(x);
    gemm_fused_kernel<<<296, 256, SMEM_BYTES>>>(x, Wl1, Wr1, b1, Wl2, Wr2);
    final_kernel<<<NN / 8, 256>>>(b2, Wt1, bt1, Wt2, bt2, out);
}

// round 12
// speedup vs baseline: 1.1134x; 1.0130x over previous
#include <cuda_runtime.h>
#include <cuda_fp16.h>

#define NN 100000
#define NE 1600000
#define SCAN_B 98           // ceil(100000 / 1024)

#define TILE_N 64
#define NTILES ((NN + TILE_N - 1) / TILE_N)   // 1563 (last tile partial)

// smem layout (floats) for fused GEMM kernel
#define W1T_SZ (8 * 1028)   // layer1 weights, 8 jt-regions, {wl,wr} interleaved, +4 pad
#define WPT_SZ (8 * 516)    // proj weights, 8 jtp-regions, {wl2,wr2} interleaved, +4 pad
#define AX_SZ  (64 * 130)   // 64 nodes x 64 k of {agg,x} float2, row 130 floats
#define SMEM_FLOATS (W1T_SZ + WPT_SZ + AX_SZ)
#define SMEM_BYTES  (SMEM_FLOATS * 4)         // 82688 B

// ---- scratch (static __device__ arrays; no allocation allowed) ----
__device__ int    g_is64;
__device__ int    g_cnt[NN];
__device__ int    g_scan[NN];
__device__ int    g_bsum[128];
__device__ int    g_rowstart[NN + 1];
__device__ int    g_cursor[NN];
__device__ int    g_csr[NE];
__device__ __half g_xh[NN * 64];   // fp16 mirror of x (gather path only)
__device__ float  g_agg1[NN * 64];
__device__ float  g_p2[NN * 32];
__device__ float  g_r2[NN * 32];

// ---- f32x2 packed helpers ----
__device__ __forceinline__ unsigned long long ffma2(
    unsigned long long a, unsigned long long b, unsigned long long c) {
    unsigned long long d;
    asm("fma.rn.f32x2 %0, %1, %2, %3;" : "=l"(d) : "l"(a), "l"(b), "l"(c));
    return d;
}
__device__ __forceinline__ unsigned long long pack2(float lo, float hi) {
    unsigned long long r;
    asm("mov.b64 %0, {%1, %2};" : "=l"(r) : "f"(lo), "f"(hi));
    return r;
}
__device__ __forceinline__ float2 unpack2(unsigned long long v) {
    float2 f;
    asm("mov.b64 {%0, %1}, %2;" : "=f"(f.x), "=f"(f.y) : "l"(v));
    return f;
}

// init: block 0 warp 0 detects int64 vs int32 edge_index (values < 1e5 so an
// int64 buffer has every odd 32-bit word == 0); all blocks zero g_cnt.
__global__ void init_kernel(const int* __restrict__ w) {
    if (blockIdx.x == 0 && threadIdx.x < 32) {
        int lane = threadIdx.x;
        int v = w[2 * lane + 1];
        unsigned m = __ballot_sync(0xffffffffu, v == 0);
        if (lane == 0) g_is64 = (m == 0xffffffffu) ? 1 : 0;
    }
    int i = blockIdx.x * blockDim.x + threadIdx.x;
    if (i < NN / 4) ((int4*)g_cnt)[i] = make_int4(0, 0, 0, 0);
}

// Count in-degrees (dst half of edge_index only) + build fp16 x mirror.
// NE == NN*16 exactly, so the same 1.6M threads cover both jobs.
__global__ void count_x2h_kernel(const void* __restrict__ e,
                                 const float* __restrict__ x) {
    int i = blockIdx.x * blockDim.x + threadIdx.x;
    if (i >= NE) return;
    int d;
    if (g_is64) d = (int)((const long long*)e)[NE + i];
    else        d = ((const int*)e)[NE + i];
    atomicAdd(&g_cnt[d], 1);
    // convert 4 x floats -> 4 halves  (i covers NN*16 = 1.6M chunks)
    float4 v = __ldg(&((const float4*)x)[i]);
    __half2* dst = (__half2*)g_xh;
    dst[2 * i]     = __floats2half2_rn(v.x, v.y);
    dst[2 * i + 1] = __floats2half2_rn(v.z, v.w);
}

__global__ void __launch_bounds__(1024) scanA_kernel() {
    __shared__ int s[1024];
    int t = threadIdx.x;
    int i = blockIdx.x * 1024 + t;
    int v = (i < NN) ? g_cnt[i] : 0;
    s[t] = v;
    __syncthreads();
#pragma unroll
    for (int off = 1; off < 1024; off <<= 1) {
        int tv = (t >= off) ? s[t - off] : 0;
        __syncthreads();
        s[t] += tv;
        __syncthreads();
    }
    if (i < NN) g_scan[i] = s[t];
    if (t == 1023) g_bsum[blockIdx.x] = s[t];
}

__global__ void __launch_bounds__(1024) scanB_kernel() {
    __shared__ int part[128];
    int t = threadIdx.x;
    if (t < 128) part[t] = (t < blockIdx.x && t < SCAN_B) ? g_bsum[t] : 0;
    __syncthreads();
#pragma unroll
    for (int off = 64; off > 0; off >>= 1) {
        if (t < off) part[t] += part[t + off];
        __syncthreads();
    }
    int offset = part[0];
    int i = blockIdx.x * 1024 + t;
    if (i < NN) {
        int rs = offset + g_scan[i] - g_cnt[i];
        g_rowstart[i] = rs;
        g_cursor[i] = rs;
    }
    if (i == 0) g_rowstart[NN] = NE;
}

// Fill CSR: read edge_index directly, convert inline.
__global__ void __launch_bounds__(256) fill_kernel(const void* __restrict__ e) {
    int i = blockIdx.x * 256 + threadIdx.x;
    if (i >= NE) return;
    int s, d;
    if (g_is64) {
        const long long* p = (const long long*)e;
        s = (int)p[i];
        d = (int)p[NE + i];
    } else {
        const int* p = (const int*)e;
        s = p[i];
        d = p[NE + i];
    }
    int pos = atomicAdd(&g_cursor[d], 1);
    g_csr[pos] = s;
}

// Gather layer 1 (fp16 x mirror): agg1[n] = mean over neighbors of xh[src].
// Thread = (node, 16B chunk of 8 halves); 8 threads/node -> 128B row reads.
// Accumulation in fp32 registers.
__global__ void __launch_bounds__(256) gather1_kernel() {
    int idx = blockIdx.x * 256 + threadIdx.x;
    int n = idx >> 3, c = idx & 7;
    if (n >= NN) return;
    int beg = __ldg(&g_rowstart[n]), end = __ldg(&g_rowstart[n + 1]);
    float acc[8];
#pragma unroll
    for (int j = 0; j < 8; j++) acc[j] = 0.f;
    const uint4* xh4 = (const uint4*)g_xh;   // 8 halves per uint4, 8 per node row
#pragma unroll 4
    for (int e = beg; e < end; e++) {
        int s = __ldg(&g_csr[e]);
        uint4 u = __ldg(&xh4[s * 8 + c]);
        float2 f0 = __half22float2(*(const __half2*)&u.x);
        float2 f1 = __half22float2(*(const __half2*)&u.y);
        float2 f2 = __half22float2(*(const __half2*)&u.z);
        float2 f3 = __half22float2(*(const __half2*)&u.w);
        acc[0] += f0.x; acc[1] += f0.y;
        acc[2] += f1.x; acc[3] += f1.y;
        acc[4] += f2.x; acc[5] += f2.y;
        acc[6] += f3.x; acc[7] += f3.y;
    }
    float inv = 1.f / fmaxf((float)(end - beg), 1.f);
    float4 o0 = make_float4(acc[0] * inv, acc[1] * inv, acc[2] * inv, acc[3] * inv);
    float4 o1 = make_float4(acc[4] * inv, acc[5] * inv, acc[6] * inv, acc[7] * inv);
    ((float4*)g_agg1)[n * 16 + c * 2]     = o0;
    ((float4*)g_agg1)[n * 16 + c * 2 + 1] = o1;
}

// Fused layer1 + proj, packed f32x2:
//   main: acc_j{aggpart,xpart} += {A,X} * {wl,wr}  -> h = relu(lo+hi+b1)
//   proj: acc_j{p2,r2} += {h,h} * {wl2,wr2}        -> g_p2, g_r2
__global__ void __launch_bounds__(256) gemm_fused_kernel(
    const float* __restrict__ x,
    const float* __restrict__ Wl1, const float* __restrict__ Wr1,
    const float* __restrict__ b1,
    const float* __restrict__ Wl2, const float* __restrict__ Wr2) {
    extern __shared__ float smem[];
    float* sW1T = smem;                 // [8][1028]
    float* sWPT = smem + W1T_SZ;        // [8][516]
    float* sAX  = smem + W1T_SZ + WPT_SZ;   // [64][130] float2-interleaved
    float* sH   = sAX;                  // overlay: [64][68] after main loop

    int tid = threadIdx.x;
    // stage layer1 weights interleaved {wl, wr}, per-jt region (pad 4 -> bank shift)
    for (int i = tid; i < 64 * 64; i += 256) {
        int k = i >> 6, j = i & 63;
        int jt = j >> 3, jj = j & 7;
        sW1T[jt * 1028 + k * 16 + jj * 2 + 0] = Wl1[k * 64 + j];
        sW1T[jt * 1028 + k * 16 + jj * 2 + 1] = Wr1[k * 64 + j];
    }
    // stage proj weights interleaved {wl2, wr2}, per-jtp region
    for (int i = tid; i < 64 * 32; i += 256) {
        int k = i >> 5, j = i & 31;
        int jtp = j >> 2, jj = j & 3;
        sWPT[jtp * 516 + k * 8 + jj * 2 + 0] = Wl2[k * 32 + j];
        sWPT[jtp * 516 + k * 8 + jj * 2 + 1] = Wr2[k * 32 + j];
    }
    int ln = tid >> 3, jt = tid & 7;    // main: 32 node-pairs x 8 j-groups(8 j each)
    float bb[8];
    {
        float4 ba = __ldg(&((const float4*)b1)[jt * 2]);
        float4 bc = __ldg(&((const float4*)b1)[jt * 2 + 1]);
        bb[0] = ba.x; bb[1] = ba.y; bb[2] = ba.z; bb[3] = ba.w;
        bb[4] = bc.x; bb[5] = bc.y; bb[6] = bc.z; bb[7] = bc.w;
    }
    const float4* agg4 = (const float4*)g_agg1;
    const float4* x4 = (const float4*)x;

    for (int tile = blockIdx.x; tile < NTILES; tile += gridDim.x) {
        int base = tile * TILE_N;
        __syncthreads();   // previous iteration's proj reads of sH done
        // stage sAX: node-local rows of {agg, x} pairs
        for (int u = tid; u < 64 * 16; u += 256) {
            int node = u >> 4, c = u & 15;     // c = float4 chunk (k = 4c..4c+3)
            int n = base + node;
            float4 a, xv;
            if (n < NN) { a = agg4[n * 16 + c]; xv = x4[n * 16 + c]; }
            else { a = make_float4(0.f,0.f,0.f,0.f); xv = a; }
            float2* dst = (float2*)(sAX + node * 130 + c * 8);
            dst[0] = make_float2(a.x, xv.x);
            dst[1] = make_float2(a.y, xv.y);
            dst[2] = make_float2(a.z, xv.z);
            dst[3] = make_float2(a.w, xv.w);
        }
        __syncthreads();
        // main GEMM: 2 nodes x 8 outputs per thread
        {
            const unsigned long long* ax0p = (const unsigned long long*)(sAX + (2 * ln) * 130);
            const unsigned long long* ax1p = (const unsigned long long*)(sAX + (2 * ln + 1) * 130);
            const unsigned long long* wp = (const unsigned long long*)(sW1T + jt * 1028);
            unsigned long long acc0[8], acc1[8];
#pragma unroll
            for (int j = 0; j < 8; j++) { acc0[j] = 0ull; acc1[j] = 0ull; }
#pragma unroll 8
            for (int k = 0; k < 64; k++) {
                unsigned long long ax0 = ax0p[k];
                unsigned long long ax1 = ax1p[k];
                ulonglong2 wA = ((const ulonglong2*)(wp + k * 8))[0];
                ulonglong2 wB = ((const ulonglong2*)(wp + k * 8))[1];
                ulonglong2 wC = ((const ulonglong2*)(wp + k * 8))[2];
                ulonglong2 wD = ((const ulonglong2*)(wp + k * 8))[3];
                acc0[0] = ffma2(ax0, wA.x, acc0[0]); acc1[0] = ffma2(ax1, wA.x, acc1[0]);
                acc0[1] = ffma2(ax0, wA.y, acc0[1]); acc1[1] = ffma2(ax1, wA.y, acc1[1]);
                acc0[2] = ffma2(ax0, wB.x, acc0[2]); acc1[2] = ffma2(ax1, wB.x, acc1[2]);
                acc0[3] = ffma2(ax0, wB.y, acc0[3]); acc1[3] = ffma2(ax1, wB.y, acc1[3]);
                acc0[4] = ffma2(ax0, wC.x, acc0[4]); acc1[4] = ffma2(ax1, wC.x, acc1[4]);
                acc0[5] = ffma2(ax0, wC.y, acc0[5]); acc1[5] = ffma2(ax1, wC.y, acc1[5]);
                acc0[6] = ffma2(ax0, wD.x, acc0[6]); acc1[6] = ffma2(ax1, wD.x, acc1[6]);
                acc0[7] = ffma2(ax0, wD.y, acc0[7]); acc1[7] = ffma2(ax1, wD.y, acc1[7]);
            }
            __syncthreads();   // all reads of sAX done before sH overlay
            float h0[8], h1[8];
#pragma unroll
            for (int j = 0; j < 8; j++) {
                float2 f0 = unpack2(acc0[j]);
                float2 f1 = unpack2(acc1[j]);
                h0[j] = fmaxf(f0.x + f0.y + bb[j], 0.f);
                h1[j] = fmaxf(f1.x + f1.y + bb[j], 0.f);
            }
            float4* d0 = (float4*)(sH + (2 * ln) * 68 + jt * 8);
            float4* d1 = (float4*)(sH + (2 * ln + 1) * 68 + jt * 8);
            d0[0] = make_float4(h0[0], h0[1], h0[2], h0[3]);
            d0[1] = make_float4(h0[4], h0[5], h0[6], h0[7]);
            d1[0] = make_float4(h1[0], h1[1], h1[2], h1[3]);
            d1[1] = make_float4(h1[4], h1[5], h1[6], h1[7]);
        }
        __syncthreads();
        // proj: 2 nodes x 4 {p2,r2}-pairs per thread
        {
            const float* h0p = sH + (2 * ln) * 68;
            const float* h1p = sH + (2 * ln + 1) * 68;
            const unsigned long long* wpp = (const unsigned long long*)(sWPT + jt * 516);
            unsigned long long pa0[4], pa1[4];
#pragma unroll
            for (int j = 0; j < 4; j++) { pa0[j] = 0ull; pa1[j] = 0ull; }
#pragma unroll 8
            for (int k = 0; k < 64; k++) {
                float hv0 = h0p[k], hv1 = h1p[k];
                unsigned long long hh0 = pack2(hv0, hv0);
                unsigned long long hh1 = pack2(hv1, hv1);
                ulonglong2 w01 = ((const ulonglong2*)(wpp + k * 4))[0];
                ulonglong2 w23 = ((const ulonglong2*)(wpp + k * 4))[1];
                pa0[0] = ffma2(hh0, w01.x, pa0[0]); pa1[0] = ffma2(hh1, w01.x, pa1[0]);
                pa0[1] = ffma2(hh0, w01.y, pa0[1]); pa1[1] = ffma2(hh1, w01.y, pa1[1]);
                pa0[2] = ffma2(hh0, w23.x, pa0[2]); pa1[2] = ffma2(hh1, w23.x, pa1[2]);
                pa0[3] = ffma2(hh0, w23.y, pa0[3]); pa1[3] = ffma2(hh1, w23.y, pa1[3]);
            }
            int n0 = base + 2 * ln, n1 = n0 + 1;
            float p0[4], r0[4], p1[4], r1[4];
#pragma unroll
            for (int j = 0; j < 4; j++) {
                float2 f0 = unpack2(pa0[j]);
                float2 f1 = unpack2(pa1[j]);
                p0[j] = f0.x; r0[j] = f0.y;
                p1[j] = f1.x; r1[j] = f1.y;
            }
            if (n0 < NN) {
                ((float4*)g_p2)[n0 * 8 + jt] = make_float4(p0[0], p0[1], p0[2], p0[3]);
                ((float4*)g_r2)[n0 * 8 + jt] = make_float4(r0[0], r0[1], r0[2], r0[3]);
            }
            if (n1 < NN) {
                ((float4*)g_p2)[n1 * 8 + jt] = make_float4(p1[0], p1[1], p1[2], p1[3]);
                ((float4*)g_r2)[n1 * 8 + jt] = make_float4(r1[0], r1[1], r1[2], r1[3]);
            }
        }
    }
}

// Final fused: gather2 (mean of p2 over neighbors) + root + bias -> out,
// then trust head (32->16 relu -> 16->1 sigmoid) via warp shuffles.
__global__ void __launch_bounds__(256) final_kernel(
    const float* __restrict__ b2, const float* __restrict__ Wt1,
    const float* __restrict__ bt1, const float* __restrict__ Wt2,
    const float* __restrict__ bt2, float* __restrict__ out) {
    __shared__ float sW1[32 * 16], sB2[32], sBt1[16], sW2[16];
    __shared__ float sBt2;
    int tid = threadIdx.x;
    sW1[tid] = Wt1[tid];
    sW1[tid + 256] = Wt1[tid + 256];
    if (tid < 32) sB2[tid] = b2[tid];
    if (tid < 16) { sBt1[tid] = bt1[tid]; sW2[tid] = Wt2[tid]; }
    if (tid == 0) sBt2 = bt2[0];
    __syncthreads();
    int warp = tid >> 5, lane = tid & 31;
    int n = blockIdx.x * 8 + warp;   // 12500 * 8 == 100000 exactly
    int beg = __ldg(&g_rowstart[n]), end = __ldg(&g_rowstart[n + 1]);
    float acc = 0.f;
#pragma unroll 4
    for (int e = beg; e < end; e++) {
        int s = __ldg(&g_csr[e]);
        acc += __ldg(&g_p2[s * 32 + lane]);
    }
    float inv = 1.f / fmaxf((float)(end - beg), 1.f);
    float v = acc * inv + g_r2[n * 32 + lane] + sB2[lane];
    out[n * 32 + lane] = v;
    float a2 = (lane < 16) ? sBt1[lane] : 0.f;
    int o = lane & 15;
#pragma unroll
    for (int j = 0; j < 32; j++) {
        float hv = __shfl_sync(0xffffffffu, v, j);
        a2 += hv * sW1[j * 16 + o];
    }
    float t = fmaxf(a2, 0.f) * sW2[o];
    t += __shfl_down_sync(0xffffffffu, t, 8);
    t += __shfl_down_sync(0xffffffffu, t, 4);
    t += __shfl_down_sync(0xffffffffu, t, 2);
    t += __shfl_down_sync(0xffffffffu, t, 1);
    if (lane == 0)
        out[NN * 32 + n] = 1.f / (1.f + __expf(-(t + sBt2)));
}

extern "C" void kernel_launch(void* const* d_in, const int* in_sizes, int n_in,
                              void* d_out, int out_size) {
    const float* x   = (const float*)d_in[0];
    const void*  ei  = d_in[1];
    const float* Wl1 = (const float*)d_in[2];
    const float* Wr1 = (const float*)d_in[3];
    const float* b1  = (const float*)d_in[4];
    const float* Wl2 = (const float*)d_in[5];
    const float* Wr2 = (const float*)d_in[6];
    const float* b2  = (const float*)d_in[7];
    const float* Wt1 = (const float*)d_in[8];
    const float* bt1 = (const float*)d_in[9];
    const float* Wt2 = (const float*)d_in[10];
    const float* bt2 = (const float*)d_in[11];
    float* out = (float*)d_out;

    cudaFuncSetAttribute(gemm_fused_kernel,
                         cudaFuncAttributeMaxDynamicSharedMemorySize, SMEM_BYTES);

    init_kernel<<<(NN / 4 + 255) / 256, 256>>>((const int*)ei);
    count_x2h_kernel<<<(NE + 255) / 256, 256>>>(ei, x);
    scanA_kernel<<<SCAN_B, 1024>>>();
    scanB_kernel<<<SCAN_B, 1024>>>();
    fill_kernel<<<(NE + 255) / 256, 256>>>(ei);
    gather1_kernel<<<(NN * 8 + 255) / 256, 256>>>();
    gemm_fused_kernel<<<296, 256, SMEM_BYTES>>>(x, Wl1, Wr1, b1, Wl2, Wr2);
    final_kernel<<<NN / 8, 256>>>(b2, Wt1, bt1, Wt2, bt2, out);
}